// round 5
// baseline (speedup 1.0000x reference)
#include <cuda_runtime.h>
#include <math.h>

// Problem constants
#define NPG     100
#define DEG     16
#define THREADS 768
#define WARPS   24
#define NGRAPH  512

typedef unsigned long long ull;

// Shared memory layout (float word offsets)
#define OFF_FSH   0                     // 10000 : feat block / agg2 staging
#define OFF_H1    10000                 // 10000 : agg1 staging then h1 (in-place)
#define OFF_W1T   20000                 // 13056 : W1 packed [128 rows][102]  (rows 100..127 uninit)
#define OFF_W2T   33056                 //  3264 : W2 packed [32 rows][102]   (rows 20..31 uninit)
#define OFF_B1    36320                 //   128
#define OFF_B2    36448                 //    32
#define OFF_H2    36480                 //  2000 : h2 [100][20]
#define OFF_SC    38480                 //   128 : epilogue scratch
#define OFF_SRC   38608                 //  1600 ints : local src indices (16B aligned)
#define SMEM_WORDS (38608 + 1600)
#define SMEM_BYTES (SMEM_WORDS * 4)

#define W1_STRIDE 102
#define W1_CHUNK  (32 * W1_STRIDE)      // 3264

// ---- packed f32x2 helpers (SASS FFMA2/FADD2/FMUL2 — PTX-only) ----
__device__ __forceinline__ ull fma2(ull a, ull b, ull c) {
    ull d; asm("fma.rn.f32x2 %0, %1, %2, %3;" : "=l"(d) : "l"(a), "l"(b), "l"(c)); return d;
}
__device__ __forceinline__ ull add2(ull a, ull b) {
    ull d; asm("add.rn.f32x2 %0, %1, %2;" : "=l"(d) : "l"(a), "l"(b)); return d;
}
__device__ __forceinline__ ull mul2(ull a, ull b) {
    ull d; asm("mul.rn.f32x2 %0, %1, %2;" : "=l"(d) : "l"(a), "l"(b)); return d;
}
__device__ __forceinline__ ull pk(float a, float b) {
    ull r; asm("mov.b64 %0, {%1, %2};" : "=l"(r) : "f"(a), "f"(b)); return r;
}
__device__ __forceinline__ float2 unpk(ull v) {
    float2 r; asm("mov.b64 {%0, %1}, %2;" : "=f"(r.x), "=f"(r.y) : "l"(v)); return r;
}
__device__ __forceinline__ ull ldp(const float* p) { return *(const ull*)p; }
__device__ __forceinline__ void stp(float* p, ull v) { *(ull*)p = v; }

// ---- per-warp phase 1: gather-mean + GEMM(W1) + bias + relu, in-place in h1 ----
template<int NBv>
__device__ __forceinline__ void phase1_tile(int n0, int lane,
    const float* __restrict__ fsh, float* __restrict__ h1sh,
    const float* __restrict__ w1t, const float* __restrict__ b1sh,
    const int* __restrict__ srcs)
{
    const ull csc = pk(0.0625f, 0.0625f);
    #pragma unroll
    for (int nb = 0; nb < NBv; nb++) {
        const int n = n0 + nb;
        ull a0 = 0ULL, a1 = 0ULL;
        const int4* sp4 = (const int4*)(srcs + n * DEG);
        #pragma unroll
        for (int k = 0; k < 4; k++) {
            int4 q = sp4[k];
            const float* r0 = fsh + q.x * 100;
            a0 = add2(a0, ldp(r0 + 2 * lane));
            a1 = add2(a1, ldp(r0 + 64 + 2 * lane));
            const float* r1 = fsh + q.y * 100;
            a0 = add2(a0, ldp(r1 + 2 * lane));
            a1 = add2(a1, ldp(r1 + 64 + 2 * lane));
            const float* r2 = fsh + q.z * 100;
            a0 = add2(a0, ldp(r2 + 2 * lane));
            a1 = add2(a1, ldp(r2 + 64 + 2 * lane));
            const float* r3 = fsh + q.w * 100;
            a0 = add2(a0, ldp(r3 + 2 * lane));
            a1 = add2(a1, ldp(r3 + 64 + 2 * lane));
        }
        float* d = h1sh + n * 100;
        stp(d + 2 * lane, mul2(a0, csc));
        if (lane < 18) stp(d + 64 + 2 * lane, mul2(a1, csc));
    }
    __syncwarp();

    ull acc[NBv][4];
    #pragma unroll
    for (int nb = 0; nb < NBv; nb++)
        #pragma unroll
        for (int c = 0; c < 4; c++) acc[nb][c] = 0ULL;

    const float* wb = w1t + lane * W1_STRIDE;
    #pragma unroll 2
    for (int i2 = 0; i2 < 50; i2++) {
        const ull w0 = ldp(wb + 2 * i2);
        const ull w1 = ldp(wb + W1_CHUNK + 2 * i2);
        const ull w2 = ldp(wb + 2 * W1_CHUNK + 2 * i2);
        const ull w3 = ldp(wb + 3 * W1_CHUNK + 2 * i2);
        #pragma unroll
        for (int nb = 0; nb < NBv; nb++) {
            const ull av = ldp(h1sh + (n0 + nb) * 100 + 2 * i2);
            acc[nb][0] = fma2(av, w0, acc[nb][0]);
            acc[nb][1] = fma2(av, w1, acc[nb][1]);
            acc[nb][2] = fma2(av, w2, acc[nb][2]);
            acc[nb][3] = fma2(av, w3, acc[nb][3]);
        }
    }
    __syncwarp();
    #pragma unroll
    for (int nb = 0; nb < NBv; nb++) {
        float* d = h1sh + (n0 + nb) * 100;
        #pragma unroll
        for (int c = 0; c < 4; c++) {
            float2 p = unpk(acc[nb][c]);
            float v = fmaxf(p.x + p.y + b1sh[lane + 32 * c], 0.f);
            if (c < 3 || lane < 4) d[lane + 32 * c] = v;
        }
    }
}

// ---- per-warp phase 2: gather-mean over h1 (stage into fsh) + GEMM(W2) + relu ----
template<int NBv>
__device__ __forceinline__ void phase2_tile(int n0, int lane,
    float* __restrict__ fsh, const float* __restrict__ h1sh,
    float* __restrict__ h2sh,
    const float* __restrict__ w2t, const float* __restrict__ b2sh,
    const int* __restrict__ srcs)
{
    const ull csc = pk(0.0625f, 0.0625f);
    #pragma unroll
    for (int nb = 0; nb < NBv; nb++) {
        const int n = n0 + nb;
        ull a0 = 0ULL, a1 = 0ULL;
        const int4* sp4 = (const int4*)(srcs + n * DEG);
        #pragma unroll
        for (int k = 0; k < 4; k++) {
            int4 q = sp4[k];
            const float* r0 = h1sh + q.x * 100;
            a0 = add2(a0, ldp(r0 + 2 * lane));
            a1 = add2(a1, ldp(r0 + 64 + 2 * lane));
            const float* r1 = h1sh + q.y * 100;
            a0 = add2(a0, ldp(r1 + 2 * lane));
            a1 = add2(a1, ldp(r1 + 64 + 2 * lane));
            const float* r2 = h1sh + q.z * 100;
            a0 = add2(a0, ldp(r2 + 2 * lane));
            a1 = add2(a1, ldp(r2 + 64 + 2 * lane));
            const float* r3 = h1sh + q.w * 100;
            a0 = add2(a0, ldp(r3 + 2 * lane));
            a1 = add2(a1, ldp(r3 + 64 + 2 * lane));
        }
        float* d = fsh + n * 100;
        stp(d + 2 * lane, mul2(a0, csc));
        if (lane < 18) stp(d + 64 + 2 * lane, mul2(a1, csc));
    }
    __syncwarp();

    ull acc[NBv];
    #pragma unroll
    for (int nb = 0; nb < NBv; nb++) acc[nb] = 0ULL;

    const float* wb = w2t + lane * W1_STRIDE;   // rows >= 20 read uninit smem (never stored)
    #pragma unroll 2
    for (int i2 = 0; i2 < 50; i2++) {
        const ull w = ldp(wb + 2 * i2);
        #pragma unroll
        for (int nb = 0; nb < NBv; nb++) {
            const ull av = ldp(fsh + (n0 + nb) * 100 + 2 * i2);
            acc[nb] = fma2(av, w, acc[nb]);
        }
    }
    if (lane < 20) {
        #pragma unroll
        for (int nb = 0; nb < NBv; nb++) {
            float2 p = unpk(acc[nb]);
            h2sh[(n0 + nb) * 20 + lane] = fmaxf(p.x + p.y + b2sh[lane], 0.f);
        }
    }
}

__global__ void __launch_bounds__(THREADS, 1) net_kernel(
    const float* __restrict__ feat, const int* __restrict__ esrc,
    const float* __restrict__ self_feat, const float* __restrict__ x3d,
    const float* __restrict__ W1, const float* __restrict__ b1,
    const float* __restrict__ W2, const float* __restrict__ b2,
    const float* __restrict__ Wv2, const float* __restrict__ Wo2,
    const float* __restrict__ g2, const float* __restrict__ be2,
    const float* __restrict__ Wv3, const float* __restrict__ Wo3,
    const float* __restrict__ g3, const float* __restrict__ be3,
    const float* __restrict__ Wf1, const float* __restrict__ bf1,
    const float* __restrict__ Wf2, const float* __restrict__ bf2,
    float* __restrict__ out)
{
    extern __shared__ float sm[];
    float* fsh  = sm + OFF_FSH;
    float* h1sh = sm + OFF_H1;
    float* w1t  = sm + OFF_W1T;
    float* w2t  = sm + OFF_W2T;
    float* b1sh = sm + OFF_B1;
    float* b2sh = sm + OFF_B2;
    float* h2sh = sm + OFF_H2;
    float* sc   = sm + OFF_SC;
    int*   srcs = (int*)(sm + OFF_SRC);

    const int g    = blockIdx.x;
    const int tid  = threadIdx.x;
    const int lane = tid & 31;
    const int warp = tid >> 5;

    // ---------------- Phase 0: stage into SMEM ----------------
    {
        const float4* f4 = (const float4*)(feat + (size_t)g * (NPG * 100));
        float4*       d4 = (float4*)fsh;
        #pragma unroll 4
        for (int i = tid; i < 2500; i += THREADS) d4[i] = f4[i];

        const int4* e4 = (const int4*)(esrc + (size_t)g * (NPG * DEG));
        int4*       s4 = (int4*)srcs;
        const int   nb0 = g * NPG;
        for (int i = tid; i < 400; i += THREADS) {
            int4 v = e4[i];
            v.x -= nb0; v.y -= nb0; v.z -= nb0; v.w -= nb0;
            s4[i] = v;
        }
        // W1 [100,100] row-major -> w1t[o*102 + i] (re-stride copy via float2)
        const ull* w1g = (const ull*)W1;
        for (int e = tid; e < 5000; e += THREADS) {
            int o = e / 50, i2 = e % 50;
            stp(w1t + o * W1_STRIDE + 2 * i2, w1g[o * 50 + i2]);
        }
        // W2 [20,100] -> w2t[o*102 + i]
        const ull* w2g = (const ull*)W2;
        for (int e = tid; e < 1000; e += THREADS) {
            int o = e / 50, i2 = e % 50;
            stp(w2t + o * W1_STRIDE + 2 * i2, w2g[o * 50 + i2]);
        }
        for (int i = tid; i < 128; i += THREADS) b1sh[i] = (i < 100) ? b1[i] : 0.f;
        if (tid < 32) b2sh[tid] = (tid < 20) ? b2[tid] : 0.f;
    }
    __syncthreads();

    // warp -> node tile: warps 0..3 own 5 nodes, warps 4..23 own 4 nodes (total 100)
    // ---------------- Phase 1 ----------------
    if (warp < 4) phase1_tile<5>(warp * 5, lane, fsh, h1sh, w1t, b1sh, srcs);
    else          phase1_tile<4>(20 + (warp - 4) * 4, lane, fsh, h1sh, w1t, b1sh, srcs);
    __syncthreads();

    // ---------------- Phase 2 ----------------
    if (warp < 4) phase2_tile<5>(warp * 5, lane, fsh, h1sh, h2sh, w2t, b2sh, srcs);
    else          phase2_tile<4>(20 + (warp - 4) * 4, lane, fsh, h1sh, h2sh, w2t, b2sh, srcs);
    __syncthreads();

    // ---------------- Phase 3 (warp 0): pool + attn2 + attn3 + MLP ----------------
    if (warp == 0) {
        if (lane < 20) {
            float s = 0.f;
            #pragma unroll 10
            for (int n = 0; n < NPG; n++) s += h2sh[n * 20 + lane];
            sc[64 + lane] = s * 0.01f;
        }
        __syncwarp();

        // ---- cross-attn 2 (len-1 softmax == identity): Z = Wo2 @ (Wv2 @ sf) ----
        {
            float v = 0.f;
            const float4* wv = (const float4*)(Wv2 + lane * 200);
            const float4* xf = (const float4*)(self_feat + (size_t)g * 200);
            #pragma unroll
            for (int j = 0; j < 50; j++) {
                float4 a = wv[j], c = xf[j];
                v = fmaf(a.x, c.x, fmaf(a.y, c.y, fmaf(a.z, c.z, fmaf(a.w, c.w, v))));
            }
            sc[lane] = v;
        }
        __syncwarp();
        float y2 = 0.f;
        if (lane < 20) {
            float z = 0.f;
            #pragma unroll
            for (int l = 0; l < 32; l++) z = fmaf(Wo2[lane * 32 + l], sc[l], z);
            y2 = sc[64 + lane] + z;
            sc[32 + lane] = y2;
        }
        __syncwarp();
        if (lane == 0) {
            float mu = 0.f;
            #pragma unroll
            for (int o = 0; o < 20; o++) mu += sc[32 + o];
            mu *= 0.05f;
            float var = 0.f;
            #pragma unroll
            for (int o = 0; o < 20; o++) { float d = sc[32 + o] - mu; var = fmaf(d, d, var); }
            var *= 0.05f;
            sc[100] = mu;
            sc[101] = 1.f / sqrtf(var + 1e-5f);
        }
        __syncwarp();
        if (lane < 20)
            sc[64 + lane] = (y2 - sc[100]) * sc[101] * g2[lane] + be2[lane];
        __syncwarp();

        // ---- cross-attn 3 ----
        {
            float v = 0.f;
            const float4* wv = (const float4*)(Wv3 + lane * 100);
            const float4* xf = (const float4*)(x3d + (size_t)g * 100);
            #pragma unroll
            for (int j = 0; j < 25; j++) {
                float4 a = wv[j], c = xf[j];
                v = fmaf(a.x, c.x, fmaf(a.y, c.y, fmaf(a.z, c.z, fmaf(a.w, c.w, v))));
            }
            sc[lane] = v;
        }
        __syncwarp();
        float y3 = 0.f;
        if (lane < 20) {
            float z = 0.f;
            #pragma unroll
            for (int l = 0; l < 32; l++) z = fmaf(Wo3[lane * 32 + l], sc[l], z);
            y3 = sc[64 + lane] + z;
            sc[32 + lane] = y3;
        }
        __syncwarp();
        if (lane == 0) {
            float mu = 0.f;
            #pragma unroll
            for (int o = 0; o < 20; o++) mu += sc[32 + o];
            mu *= 0.05f;
            float var = 0.f;
            #pragma unroll
            for (int o = 0; o < 20; o++) { float d = sc[32 + o] - mu; var = fmaf(d, d, var); }
            var *= 0.05f;
            sc[100] = mu;
            sc[101] = 1.f / sqrtf(var + 1e-5f);
        }
        __syncwarp();
        if (lane < 20)
            sc[64 + lane] = (y3 - sc[100]) * sc[101] * g3[lane] + be3[lane];
        __syncwarp();

        // ---- MLP head ----
        if (lane < 10) {
            float f = bf1[lane];
            #pragma unroll
            for (int o = 0; o < 20; o++) f = fmaf(Wf1[lane * 20 + o], sc[64 + o], f);
            sc[84 + lane] = fmaxf(f, 0.f);
        }
        __syncwarp();
        if (lane == 0) {
            float r = bf2[0];
            #pragma unroll
            for (int k = 0; k < 10; k++) r = fmaf(Wf2[k], sc[84 + k], r);
            out[g] = r;
        }
    }
}

extern "C" void kernel_launch(void* const* d_in, const int* in_sizes, int n_in,
                              void* d_out, int out_size)
{
    const float* feat      = (const float*)d_in[0];
    const int*   esrc      = (const int*)  d_in[1];
    const float* self_feat = (const float*)d_in[3];
    const float* x3d       = (const float*)d_in[4];
    const float* W1  = (const float*)d_in[5];
    const float* b1  = (const float*)d_in[6];
    const float* W2  = (const float*)d_in[7];
    const float* b2  = (const float*)d_in[8];
    const float* Wv2 = (const float*)d_in[11];
    const float* Wo2 = (const float*)d_in[12];
    const float* g2  = (const float*)d_in[13];
    const float* be2 = (const float*)d_in[14];
    const float* Wv3 = (const float*)d_in[17];
    const float* Wo3 = (const float*)d_in[18];
    const float* g3  = (const float*)d_in[19];
    const float* be3 = (const float*)d_in[20];
    const float* Wf1 = (const float*)d_in[21];
    const float* bf1 = (const float*)d_in[22];
    const float* Wf2 = (const float*)d_in[23];
    const float* bf2 = (const float*)d_in[24];
    float* out = (float*)d_out;

    cudaFuncSetAttribute(net_kernel, cudaFuncAttributeMaxDynamicSharedMemorySize, SMEM_BYTES);
    net_kernel<<<NGRAPH, THREADS, SMEM_BYTES>>>(
        feat, esrc, self_feat, x3d,
        W1, b1, W2, b2,
        Wv2, Wo2, g2, be2,
        Wv3, Wo3, g3, be3,
        Wf1, bf1, Wf2, bf2, out);
}

// round 9
// speedup vs baseline: 1.8391x; 1.8391x over previous
#include <cuda_runtime.h>
#include <math.h>

// Problem constants
#define NPG     100
#define DEG     16
#define THREADS 512
#define WARPS   16
#define NGRAPH  512

// Shared memory layout (float word offsets)
#define OFF_FSH   0         // 10000 : feat block, then z staging in phase 2
#define OFF_H1    10000     // 10000 : agg1 staging then h1 (in-place)
#define OFF_W1    20000     // 12800 : W1 [128 rows][100] row-major (rows 100..127 zero)
#define OFF_W2    32800     //  3200 : W2 [32 rows][100]  row-major (rows 20..31 zero)
#define OFF_B1    36000     //   128
#define OFF_B2    36128     //    32
#define OFF_H2    36160     //  2000 : h2 [100][20]
#define OFF_SC    38160     //   128 : epilogue scratch
#define OFF_SRC   38288     //  1600 ints : local src indices
#define SMEM_WORDS (38288 + 1600)
#define SMEM_BYTES (SMEM_WORDS * 4)

// ---- phase 1: gather-mean (float4) + GEMM(W1) + bias + relu, in-place in h1 ----
template<int NBv>
__device__ __forceinline__ void phase1_tile(int n0, int lane,
    const float* __restrict__ fsh, float* __restrict__ h1sh,
    const float* __restrict__ w1sh, const float* __restrict__ b1sh,
    const int* __restrict__ srcs)
{
    const float4* f4 = (const float4*)fsh;
    float4*       h4 = (float4*)h1sh;

    // gather-mean: lane < 25 covers all 100 dims as float4
    #pragma unroll
    for (int nb = 0; nb < NBv; nb++) {
        const int n = n0 + nb;
        const int4* sp4 = (const int4*)(srcs + n * DEG);
        if (lane < 25) {
            float4 a = make_float4(0.f, 0.f, 0.f, 0.f);
            #pragma unroll
            for (int k = 0; k < 4; k++) {
                int4 q = sp4[k];
                float4 v0 = f4[q.x * 25 + lane];
                float4 v1 = f4[q.y * 25 + lane];
                float4 v2 = f4[q.z * 25 + lane];
                float4 v3 = f4[q.w * 25 + lane];
                a.x += v0.x + v1.x + v2.x + v3.x;
                a.y += v0.y + v1.y + v2.y + v3.y;
                a.z += v0.z + v1.z + v2.z + v3.z;
                a.w += v0.w + v1.w + v2.w + v3.w;
            }
            a.x *= 0.0625f; a.y *= 0.0625f; a.z *= 0.0625f; a.w *= 0.0625f;
            h4[n * 25 + lane] = a;
        }
    }
    __syncwarp();

    // GEMM: lane = output o (4 chunks: o, o+32, o+64, o+96; rows >=100 are zero-padded)
    float acc[NBv][4];
    #pragma unroll
    for (int nb = 0; nb < NBv; nb++)
        #pragma unroll
        for (int c = 0; c < 4; c++) acc[nb][c] = 0.f;

    const float4* w4 = (const float4*)w1sh;
    const int r0 = lane * 25, r1 = (lane + 32) * 25, r2 = (lane + 64) * 25, r3 = (lane + 96) * 25;
    #pragma unroll 5
    for (int i4 = 0; i4 < 25; i4++) {
        const float4 w0 = w4[r0 + i4];
        const float4 w1 = w4[r1 + i4];
        const float4 w2 = w4[r2 + i4];
        const float4 w3 = w4[r3 + i4];
        #pragma unroll
        for (int nb = 0; nb < NBv; nb++) {
            const float4 av = h4[(n0 + nb) * 25 + i4];
            acc[nb][0] = fmaf(av.x, w0.x, fmaf(av.y, w0.y, fmaf(av.z, w0.z, fmaf(av.w, w0.w, acc[nb][0]))));
            acc[nb][1] = fmaf(av.x, w1.x, fmaf(av.y, w1.y, fmaf(av.z, w1.z, fmaf(av.w, w1.w, acc[nb][1]))));
            acc[nb][2] = fmaf(av.x, w2.x, fmaf(av.y, w2.y, fmaf(av.z, w2.z, fmaf(av.w, w2.w, acc[nb][2]))));
            acc[nb][3] = fmaf(av.x, w3.x, fmaf(av.y, w3.y, fmaf(av.z, w3.z, fmaf(av.w, w3.w, acc[nb][3]))));
        }
    }
    __syncwarp();
    #pragma unroll
    for (int nb = 0; nb < NBv; nb++) {
        float* d = h1sh + (n0 + nb) * 100;
        d[lane]      = fmaxf(acc[nb][0] + b1sh[lane],      0.f);
        d[lane + 32] = fmaxf(acc[nb][1] + b1sh[lane + 32], 0.f);
        d[lane + 64] = fmaxf(acc[nb][2] + b1sh[lane + 64], 0.f);
        if (lane < 4) d[lane + 96] = fmaxf(acc[nb][3] + b1sh[lane + 96], 0.f);
    }
}

// ---- phase 2a: multiply-first z = h1 @ W2^T (no bias/relu yet) -> zsh [n][20] ----
template<int NBv>
__device__ __forceinline__ void phase2_mul(int n0, int lane,
    const float* __restrict__ h1sh, float* __restrict__ zsh,
    const float* __restrict__ w2sh)
{
    const float4* h4 = (const float4*)h1sh;
    const float4* w4 = (const float4*)w2sh;
    float acc[NBv];
    #pragma unroll
    for (int nb = 0; nb < NBv; nb++) acc[nb] = 0.f;

    const int rw = lane * 25;    // rows 20..31 are zero-padded -> unguarded
    #pragma unroll 5
    for (int i4 = 0; i4 < 25; i4++) {
        const float4 w = w4[rw + i4];
        #pragma unroll
        for (int nb = 0; nb < NBv; nb++) {
            const float4 av = h4[(n0 + nb) * 25 + i4];
            acc[nb] = fmaf(av.x, w.x, fmaf(av.y, w.y, fmaf(av.z, w.z, fmaf(av.w, w.w, acc[nb]))));
        }
    }
    if (lane < 20) {
        #pragma unroll
        for (int nb = 0; nb < NBv; nb++)
            zsh[(n0 + nb) * 20 + lane] = acc[nb];
    }
}

// ---- phase 2b: gather-mean z over neighbors (20-dim) + bias + relu -> h2 ----
template<int NBv>
__device__ __forceinline__ void phase2_gather(int n0, int lane,
    const float* __restrict__ zsh, float* __restrict__ h2sh,
    const float* __restrict__ b2sh, const int* __restrict__ srcs)
{
    if (lane >= 20) return;
    #pragma unroll
    for (int nb = 0; nb < NBv; nb++) {
        const int n = n0 + nb;
        const int4* sp4 = (const int4*)(srcs + n * DEG);
        float s = 0.f;
        #pragma unroll
        for (int k = 0; k < 4; k++) {
            int4 q = sp4[k];
            s += zsh[q.x * 20 + lane];
            s += zsh[q.y * 20 + lane];
            s += zsh[q.z * 20 + lane];
            s += zsh[q.w * 20 + lane];
        }
        h2sh[n * 20 + lane] = fmaxf(s * 0.0625f + b2sh[lane], 0.f);
    }
}

__global__ void __launch_bounds__(THREADS, 1) net_kernel(
    const float* __restrict__ feat, const int* __restrict__ esrc,
    const float* __restrict__ self_feat, const float* __restrict__ x3d,
    const float* __restrict__ W1, const float* __restrict__ b1,
    const float* __restrict__ W2, const float* __restrict__ b2,
    const float* __restrict__ Wv2, const float* __restrict__ Wo2,
    const float* __restrict__ g2, const float* __restrict__ be2,
    const float* __restrict__ Wv3, const float* __restrict__ Wo3,
    const float* __restrict__ g3, const float* __restrict__ be3,
    const float* __restrict__ Wf1, const float* __restrict__ bf1,
    const float* __restrict__ Wf2, const float* __restrict__ bf2,
    float* __restrict__ out)
{
    extern __shared__ float sm[];
    float* fsh  = sm + OFF_FSH;
    float* h1sh = sm + OFF_H1;
    float* w1sh = sm + OFF_W1;
    float* w2sh = sm + OFF_W2;
    float* b1sh = sm + OFF_B1;
    float* b2sh = sm + OFF_B2;
    float* h2sh = sm + OFF_H2;
    float* sc   = sm + OFF_SC;
    int*   srcs = (int*)(sm + OFF_SRC);

    const int g    = blockIdx.x;
    const int tid  = threadIdx.x;
    const int lane = tid & 31;
    const int warp = tid >> 5;

    // ---------------- Phase 0: stage into SMEM ----------------
    {
        const float4* f4 = (const float4*)(feat + (size_t)g * (NPG * 100));
        float4*       d4 = (float4*)fsh;
        #pragma unroll 4
        for (int i = tid; i < 2500; i += THREADS) d4[i] = f4[i];

        const int4* e4 = (const int4*)(esrc + (size_t)g * (NPG * DEG));
        int4*       s4 = (int4*)srcs;
        const int   nb0 = g * NPG;
        for (int i = tid; i < 400; i += THREADS) {
            int4 v = e4[i];
            v.x -= nb0; v.y -= nb0; v.z -= nb0; v.w -= nb0;
            s4[i] = v;
        }
        // W1 [100,100] row-major -> w1sh rows 0..99 (direct copy), rows 100..127 zero
        const float4* w1g = (const float4*)W1;
        float4*       w1d = (float4*)w1sh;
        for (int e = tid; e < 2500; e += THREADS) w1d[e] = w1g[e];
        for (int e = tid; e < 700;  e += THREADS) w1d[2500 + e] = make_float4(0.f,0.f,0.f,0.f);
        // W2 [20,100] -> w2sh rows 0..19, rows 20..31 zero
        const float4* w2g = (const float4*)W2;
        float4*       w2d = (float4*)w2sh;
        for (int e = tid; e < 500; e += THREADS) w2d[e] = w2g[e];
        for (int e = tid; e < 300; e += THREADS) w2d[500 + e] = make_float4(0.f,0.f,0.f,0.f);

        for (int i = tid; i < 128; i += THREADS) b1sh[i] = (i < 100) ? b1[i] : 0.f;
        if (tid < 32) b2sh[tid] = (tid < 20) ? b2[tid] : 0.f;
    }
    __syncthreads();

    // warp -> node tile: warps 0..3 own 7 nodes, warps 4..15 own 6 (4*7+12*6=100)
    const int n0  = (warp < 4) ? warp * 7 : 28 + (warp - 4) * 6;

    // ---------------- Phase 1 ----------------
    if (warp < 4) phase1_tile<7>(n0, lane, fsh, h1sh, w1sh, b1sh, srcs);
    else          phase1_tile<6>(n0, lane, fsh, h1sh, w1sh, b1sh, srcs);
    __syncthreads();   // protect fsh reuse (z) vs phase-1 gather reads

    // ---------------- Phase 2a: multiply first ----------------
    if (warp < 4) phase2_mul<7>(n0, lane, h1sh, fsh, w2sh);
    else          phase2_mul<6>(n0, lane, h1sh, fsh, w2sh);
    __syncthreads();   // all z ready before cross-node gather

    // ---------------- Phase 2b: gather 20-dim ----------------
    if (warp < 4) phase2_gather<7>(n0, lane, fsh, h2sh, b2sh, srcs);
    else          phase2_gather<6>(n0, lane, fsh, h2sh, b2sh, srcs);
    __syncthreads();

    // ---------------- Phase 3 (warp 0): pool + attn2 + attn3 + MLP ----------------
    if (warp == 0) {
        if (lane < 20) {
            float s = 0.f;
            #pragma unroll 10
            for (int n = 0; n < NPG; n++) s += h2sh[n * 20 + lane];
            sc[64 + lane] = s * 0.01f;
        }
        __syncwarp();

        // ---- cross-attn 2 (len-1 softmax == identity): Z = Wo2 @ (Wv2 @ sf) ----
        {
            float v = 0.f;
            const float4* wv = (const float4*)(Wv2 + lane * 200);
            const float4* xf = (const float4*)(self_feat + (size_t)g * 200);
            #pragma unroll
            for (int j = 0; j < 50; j++) {
                float4 a = wv[j], c = xf[j];
                v = fmaf(a.x, c.x, fmaf(a.y, c.y, fmaf(a.z, c.z, fmaf(a.w, c.w, v))));
            }
            sc[lane] = v;
        }
        __syncwarp();
        float y2 = 0.f;
        if (lane < 20) {
            float z = 0.f;
            #pragma unroll
            for (int l = 0; l < 32; l++) z = fmaf(Wo2[lane * 32 + l], sc[l], z);
            y2 = sc[64 + lane] + z;
            sc[32 + lane] = y2;
        }
        __syncwarp();
        if (lane == 0) {
            float mu = 0.f;
            #pragma unroll
            for (int o = 0; o < 20; o++) mu += sc[32 + o];
            mu *= 0.05f;
            float var = 0.f;
            #pragma unroll
            for (int o = 0; o < 20; o++) { float d = sc[32 + o] - mu; var = fmaf(d, d, var); }
            var *= 0.05f;
            sc[100] = mu;
            sc[101] = 1.f / sqrtf(var + 1e-5f);
        }
        __syncwarp();
        if (lane < 20)
            sc[64 + lane] = (y2 - sc[100]) * sc[101] * g2[lane] + be2[lane];
        __syncwarp();

        // ---- cross-attn 3 ----
        {
            float v = 0.f;
            const float4* wv = (const float4*)(Wv3 + lane * 100);
            const float4* xf = (const float4*)(x3d + (size_t)g * 100);
            #pragma unroll
            for (int j = 0; j < 25; j++) {
                float4 a = wv[j], c = xf[j];
                v = fmaf(a.x, c.x, fmaf(a.y, c.y, fmaf(a.z, c.z, fmaf(a.w, c.w, v))));
            }
            sc[lane] = v;
        }
        __syncwarp();
        float y3 = 0.f;
        if (lane < 20) {
            float z = 0.f;
            #pragma unroll
            for (int l = 0; l < 32; l++) z = fmaf(Wo3[lane * 32 + l], sc[l], z);
            y3 = sc[64 + lane] + z;
            sc[32 + lane] = y3;
        }
        __syncwarp();
        if (lane == 0) {
            float mu = 0.f;
            #pragma unroll
            for (int o = 0; o < 20; o++) mu += sc[32 + o];
            mu *= 0.05f;
            float var = 0.f;
            #pragma unroll
            for (int o = 0; o < 20; o++) { float d = sc[32 + o] - mu; var = fmaf(d, d, var); }
            var *= 0.05f;
            sc[100] = mu;
            sc[101] = 1.f / sqrtf(var + 1e-5f);
        }
        __syncwarp();
        if (lane < 20)
            sc[64 + lane] = (y3 - sc[100]) * sc[101] * g3[lane] + be3[lane];
        __syncwarp();

        // ---- MLP head ----
        if (lane < 10) {
            float f = bf1[lane];
            #pragma unroll
            for (int o = 0; o < 20; o++) f = fmaf(Wf1[lane * 20 + o], sc[64 + o], f);
            sc[84 + lane] = fmaxf(f, 0.f);
        }
        __syncwarp();
        if (lane == 0) {
            float r = bf2[0];
            #pragma unroll
            for (int k = 0; k < 10; k++) r = fmaf(Wf2[k], sc[84 + k], r);
            out[g] = r;
        }
    }
}

extern "C" void kernel_launch(void* const* d_in, const int* in_sizes, int n_in,
                              void* d_out, int out_size)
{
    const float* feat      = (const float*)d_in[0];
    const int*   esrc      = (const int*)  d_in[1];
    const float* self_feat = (const float*)d_in[3];
    const float* x3d       = (const float*)d_in[4];
    const float* W1  = (const float*)d_in[5];
    const float* b1  = (const float*)d_in[6];
    const float* W2  = (const float*)d_in[7];
    const float* b2  = (const float*)d_in[8];
    const float* Wv2 = (const float*)d_in[11];
    const float* Wo2 = (const float*)d_in[12];
    const float* g2  = (const float*)d_in[13];
    const float* be2 = (const float*)d_in[14];
    const float* Wv3 = (const float*)d_in[17];
    const float* Wo3 = (const float*)d_in[18];
    const float* g3  = (const float*)d_in[19];
    const float* be3 = (const float*)d_in[20];
    const float* Wf1 = (const float*)d_in[21];
    const float* bf1 = (const float*)d_in[22];
    const float* Wf2 = (const float*)d_in[23];
    const float* bf2 = (const float*)d_in[24];
    float* out = (float*)d_out;

    cudaFuncSetAttribute(net_kernel, cudaFuncAttributeMaxDynamicSharedMemorySize, SMEM_BYTES);
    net_kernel<<<NGRAPH, THREADS, SMEM_BYTES>>>(
        feat, esrc, self_feat, x3d,
        W1, b1, W2, b2,
        Wv2, Wo2, g2, be2,
        Wv3, Wo3, g3, be3,
        Wf1, bf1, Wf2, bf2, out);
}